// round 16
// baseline (speedup 1.0000x reference)
#include <cuda_runtime.h>

// Random_RNN two-hop — algebraic collapse: out = (W2*W1) * x^T.
//   k1 build: EXACT R11 scan (1184x256 flat int4 scan; scalar hop1 pass —
//             vectorizing it cost +1.2us in R15; ILP-2 cost +3.6us in R14).
//   k2 fold+gemm fused: 256 blocks x 512. 16 warps fold 16 j's (shfl-
//             broadcast inner loop, spread RED atomics into dense M), one
//             self-resetting counter grid barrier, then block o GEMMs M row o.
// Invariants: line-padded counters (L2 atomics serialize per 128B line),
// counters consumed-and-reset, barrier counters return to 0, M zeroed in k1
// -> every launch/replay sees identical state.

#define B      128
#define IN_F   256
#define N_ASS  4096
#define OUT_F  256
#define ASS0   256
#define OUT0   (IN_F + N_ASS)   // 4352
#define CAP1   40               // per-j in-degree  (E 12.8, sd 3.5)
#define CAP2   40               // per-j out-degree to outputs (E 12.8, sd 3.5)
#define XT_N   (IN_F * B)       // 32768
#define MSZ    (OUT_F * IN_F)   // 65536
#define CSTR   32               // counter stride: 32 ints = 128B = 1 L2 line
#define K2BLK  256

__device__ float2       g_b1[N_ASS * CAP1];  // in-edges of j:  {s (int bits), w1}
__device__ float2       g_b2[N_ASS * CAP2];  // out-edges of j: {o (int bits), w2}
__device__ int          g_c1[N_ASS * CSTR];  // one counter per L2 line
__device__ int          g_c2[N_ASS * CSTR];
__device__ float        g_xT[IN_F * B];      // x transposed [s][b]
__device__ float        g_M[MSZ];            // dense W2*W1, [o][s]
__device__ int          g_arrive;            // barrier counters; both return
__device__ int          g_exit;              // to 0 every launch

// ---------------------------------------------------------------- k1: build
// EXACT R11 scan shape (best measured: 9.7us).
__global__ void __launch_bounds__(256, 8)
k_build(const float* __restrict__ x,
        const int* __restrict__ in_src, const int* __restrict__ in_dst,
        const float* __restrict__ in_w, int E_in,
        const int* __restrict__ a_src, const int* __restrict__ a_dst,
        const float* __restrict__ a_w, int E_ass) {
    const int i  = blockIdx.x * 256 + threadIdx.x;
    const int nt = gridDim.x * 256;                    // 303104

    if (i < MSZ) g_M[i] = 0.f;                         // nt > MSZ: one shot

    // x [B][IN_F] -> xT [IN_F][B]
    for (int idx = i; idx < XT_N; idx += nt) {
        int b = idx >> 8, s = idx & 255;               // IN_F == 256
        g_xT[s * B + b] = x[idx];
    }

    // hop1 edges (~52K): scalar pass (pinned), bucket by dst assoc j
    for (int e = i; e < E_in; e += nt) {
        int   j = in_dst[e] - ASS0;
        int   s = in_src[e];
        float w = in_w[e];
        int pos = atomicAdd(&g_c1[j * CSTR], 1);
        g_b1[j * CAP1 + pos] = make_float2(__int_as_float(s), w);
    }

    // hop2 edges (~891K): flat int4 dst scan, filter dst >= OUT0, key by SRC j
    const int     E4  = E_ass >> 2;
    const int4*   a4  = (const int4*)a_dst;
    const int4*   s4p = (const int4*)a_src;
    const float4* w4p = (const float4*)a_w;
    for (int q = i; q < E4; q += nt) {
        int4 d4 = __ldg(&a4[q]);
        if (d4.x >= OUT0 || d4.y >= OUT0 || d4.z >= OUT0 || d4.w >= OUT0) {
            int4   s4 = __ldg(&s4p[q]);                // conditional side loads
            float4 w4 = __ldg(&w4p[q]);
            int   dd[4] = {d4.x, d4.y, d4.z, d4.w};
            int   ss[4] = {s4.x, s4.y, s4.z, s4.w};
            float ww[4] = {w4.x, w4.y, w4.z, w4.w};
#pragma unroll
            for (int m = 0; m < 4; m++) {
                if (dd[m] >= OUT0) {
                    int j   = ss[m] - ASS0;            // key by source assoc
                    int o   = dd[m] - OUT0;
                    int pos = atomicAdd(&g_c2[j * CSTR], 1);
                    g_b2[j * CAP2 + pos] =
                        make_float2(__int_as_float(o), ww[m]);
                }
            }
        }
    }
    for (int e = (E4 << 2) + i; e < E_ass; e += nt) {  // tail (E_ass % 4)
        int d = a_dst[e];
        if (d >= OUT0) {
            int   j = a_src[e] - ASS0;
            int   o = d - OUT0;
            float w = a_w[e];
            int pos = atomicAdd(&g_c2[j * CSTR], 1);
            g_b2[j * CAP2 + pos] = make_float2(__int_as_float(o), w);
        }
    }
}

// ---------------------------------------------------------------- k2: fold + gemm
// 256 blocks x 512 threads, one resident wave (<=32 regs -> 4 CTA/SM).
__global__ void __launch_bounds__(512) k_fold_gemm(float* __restrict__ out) {
    const int tid  = threadIdx.x;
    const int warp = tid >> 5, lane = tid & 31;

    // ---- fold: warp w folds j = blockIdx*16 + w (16 warps -> all 4096 j) ----
    {
        int j  = blockIdx.x * 16 + warp;
        int n1 = __ldg(&g_c1[j * CSTR]);
        int n2 = __ldg(&g_c2[j * CSTR]);
        if (lane == 0) { g_c1[j * CSTR] = 0; g_c2[j * CSTR] = 0; }  // consume+reset
        const float2* e1 = &g_b1[j * CAP1];
        const float2* e2 = &g_b2[j * CAP2];

        float2 my2 = (lane < n2) ? __ldg(&e2[lane]) : make_float2(0.f, 0.f);
        float2 my1 = (lane < n1) ? __ldg(&e1[lane]) : make_float2(0.f, 0.f);
        int   s  = __float_as_int(my1.x);
        float w1 = my1.y;
        int nb = (n2 < 32) ? n2 : 32;
        for (int k = 0; k < nb; k++) {                 // register broadcast
            int   o  = __shfl_sync(0xffffffffu, __float_as_int(my2.x), k);
            float w2 = __shfl_sync(0xffffffffu, my2.y, k);
            if (lane < n1)
                atomicAdd(&g_M[o * IN_F + s], w1 * w2);   // RED, spread addrs
        }
        for (int k = 32; k < n2; k++) {                // ultra-rare overflow
            float2 p2 = __ldg(&e2[k]);
            if (lane < n1)
                atomicAdd(&g_M[__float_as_int(p2.x) * IN_F + s], w1 * p2.y);
        }
        for (int t = lane + 32; t < n1; t += 32) {     // n1>32 impossible; safe
            float2 p1 = __ldg(&e1[t]);
            int   s2  = __float_as_int(p1.x);
            for (int k = 0; k < n2; k++) {
                float2 p2 = __ldg(&e2[k]);
                atomicAdd(&g_M[__float_as_int(p2.x) * IN_F + s2], p1.y * p2.y);
            }
        }
    }

    // ---- grid barrier: double-counter, self-resetting (replay-safe) ----
    __threadfence();                                   // publish this thread's REDs
    __syncthreads();
    if (tid == 0) {
        atomicAdd(&g_arrive, 1);
        while (*((volatile int*)&g_arrive) < K2BLK) {}
        // exit phase: last block out resets both counters to 0
        if (atomicAdd(&g_exit, 1) == K2BLK - 1) { g_arrive = 0; g_exit = 0; }
    }
    __syncthreads();
    __threadfence();                                   // acquire peers' REDs

    // ---- gemm: out[b][o] = sum_s M[o][s] * xT[s][b], o = blockIdx ----
    {
        __shared__ float sM[IN_F];
        __shared__ float part[3][B];
        int o = blockIdx.x;
        int g = tid >> 7, b = tid & 127;
        for (int s = tid; s < IN_F; s += 512) sM[s] = g_M[o * IN_F + s];
        __syncthreads();
        float r = 0.f;
        int s0 = g * 64;
#pragma unroll
        for (int sr = 0; sr < 64; sr += 8) {           // 8 independent loads
            float v[8];
#pragma unroll
            for (int k = 0; k < 8; k++)
                v[k] = g_xT[(s0 + sr + k) * B + b];
#pragma unroll
            for (int k = 0; k < 8; k++)
                r += sM[s0 + sr + k] * v[k];
        }
        if (g > 0) part[g - 1][b] = r;
        __syncthreads();
        if (g == 0)
            out[b * OUT_F + o] = r + part[0][b] + part[1][b] + part[2][b];
    }
}

// ---------------------------------------------------------------- launch
extern "C" void kernel_launch(void* const* d_in, const int* in_sizes, int n_in,
                              void* d_out, int out_size) {
    const float* x      = (const float*)d_in[0];
    const float* in_w   = (const float*)d_in[1];
    const float* a_w    = (const float*)d_in[2];
    const int*   in_src = (const int*)d_in[3];
    const int*   in_dst = (const int*)d_in[4];
    const int*   a_src  = (const int*)d_in[5];
    const int*   a_dst  = (const int*)d_in[6];
    int E_in  = in_sizes[1];
    int E_ass = in_sizes[2];
    float* out = (float*)d_out;

    k_build    <<<1184, 256>>>(x, in_src, in_dst, in_w, E_in,
                               a_src, a_dst, a_w, E_ass);
    k_fold_gemm<<<K2BLK, 512>>>(out);
}